// round 6
// baseline (speedup 1.0000x reference)
#include <cuda_runtime.h>
#include <cuda_bf16.h>
#include <cstdint>

// ============================================================================
// BinaryLinearLayer: out = sign(X) @ sign(W) * scale
// R3 evidence: GEMM was issue/latency-bound (tensor 52.3%, occ 12.5%, issue
// 29.7%, DRAM 3.3%). R4/R5 changes:
//   * 512-thread CTA (16 warps, 4/SMSP) with CTA tile 128x256 (warp 64x32)
//   * single __syncthreads per k-tile (wait -> sync -> fill(it+2) -> compute)
//   * STAGES=3 ring (144 KB SMEM)
// ============================================================================

#define DINL __device__ __forceinline__

static constexpr int Mdim = 8192, Ndim = 2048, Kdim = 4096;
static constexpr int TM = 128, TN = 256, TK = 128;       // int8: 128 B per K-row
static constexpr int STAGES = 3;
static constexpr int KITERS = Kdim / TK;                 // 32
static constexpr int A_BYTES = TM * TK;                  // 16384
static constexpr int B_BYTES = TN * TK;                  // 32768
static constexpr int STAGE_BYTES = A_BYTES + B_BYTES;    // 49152
static constexpr int SMEM_BYTES = STAGES * STAGE_BYTES;  // 147456

// ---------------------------------------------------------------------------
// Scratch (module globals; no runtime allocation)
// ---------------------------------------------------------------------------
__device__ int8_t g_Xs[(size_t)Mdim * Kdim];   // 32 MB  sign(X) int8 [M,K]
__device__ int8_t g_Wt[(size_t)Ndim * Kdim];   //  8 MB  sign(W)^T int8 [N,K]
__device__ float  g_scale[Ndim];

// ---------------------------------------------------------------------------
// PTX helpers (portable under target sm_100; no 'a'-suffix features)
// ---------------------------------------------------------------------------
DINL uint32_t smem_u32(const void* p) {
    uint32_t a;
    asm("{ .reg .u64 t; cvta.to.shared.u64 t, %1; cvt.u32.u64 %0, t; }" : "=r"(a) : "l"(p));
    return a;
}

DINL void cp_async16(uint32_t dst, const void* src) {
    asm volatile("cp.async.cg.shared.global [%0], [%1], 16;" :: "r"(dst), "l"(src));
}
DINL void cp_commit() { asm volatile("cp.async.commit_group;" ::: "memory"); }
#define CP_WAIT_GROUP(N) asm volatile("cp.async.wait_group %0;" :: "n"(N) : "memory")

DINL void ldmatrix_x4(uint32_t& r0, uint32_t& r1, uint32_t& r2, uint32_t& r3,
                      uint32_t addr) {
    asm volatile("ldmatrix.sync.aligned.m8n8.x4.shared.b16 {%0,%1,%2,%3}, [%4];"
                 : "=r"(r0), "=r"(r1), "=r"(r2), "=r"(r3) : "r"(addr));
}

DINL void imma(int& c0, int& c1, int& c2, int& c3,
               uint32_t a0, uint32_t a1, uint32_t a2, uint32_t a3,
               uint32_t b0, uint32_t b1) {
    asm volatile(
        "mma.sync.aligned.m16n8k32.row.col.s32.s8.s8.s32 "
        "{%0,%1,%2,%3}, {%4,%5,%6,%7}, {%8,%9}, {%0,%1,%2,%3};"
        : "+r"(c0), "+r"(c1), "+r"(c2), "+r"(c3)
        : "r"(a0), "r"(a1), "r"(a2), "r"(a3), "r"(b0), "r"(b1));
}

// byte-offset swizzle within 128B rows: spreads 8 rows across 16B banks
DINL uint32_t swz(uint32_t row, uint32_t kb) {   // kb < 128
    return row * 128u + (kb ^ ((row & 7u) << 4));
}

DINL int8_t sign_s8(float x) {
    return (int8_t)((x > 0.0f) - (x < 0.0f));    // sign(0) = 0, like jnp.sign
}

// ---------------------------------------------------------------------------
// Prepass kernels
// ---------------------------------------------------------------------------
__global__ void conv_x_kernel(const float* __restrict__ X) {
    size_t i = (size_t)blockIdx.x * blockDim.x + threadIdx.x;
    const float4* src = reinterpret_cast<const float4*>(X) + i * 2;
    float4 v0 = src[0], v1 = src[1];
    uint32_t lo = ((uint32_t)(uint8_t)sign_s8(v0.x)) |
                  ((uint32_t)(uint8_t)sign_s8(v0.y) << 8) |
                  ((uint32_t)(uint8_t)sign_s8(v0.z) << 16) |
                  ((uint32_t)(uint8_t)sign_s8(v0.w) << 24);
    uint32_t hi = ((uint32_t)(uint8_t)sign_s8(v1.x)) |
                  ((uint32_t)(uint8_t)sign_s8(v1.y) << 8) |
                  ((uint32_t)(uint8_t)sign_s8(v1.z) << 16) |
                  ((uint32_t)(uint8_t)sign_s8(v1.w) << 24);
    reinterpret_cast<uint2*>(g_Xs)[i] = make_uint2(lo, hi);
}

__global__ void conv_w_kernel(const float* __restrict__ W) {
    // W [4096(K), 2048(N)] row-major -> g_Wt [N, K] int8 signs (transposed)
    __shared__ float tile[32][33];
    int n0 = blockIdx.x * 32;   // along N
    int k0 = blockIdx.y * 32;   // along K
    int tx = threadIdx.x, ty = threadIdx.y;            // 32 x 8
    #pragma unroll
    for (int i = ty; i < 32; i += 8)
        tile[i][tx] = W[(size_t)(k0 + i) * Ndim + n0 + tx];
    __syncthreads();
    #pragma unroll
    for (int i = ty; i < 32; i += 8) {
        float v = tile[tx][i];                         // = W[k0+tx][n0+i]
        g_Wt[(size_t)(n0 + i) * Kdim + k0 + tx] = sign_s8(v);
    }
}

__global__ void conv_scale_kernel(const float* __restrict__ alpha,
                                  const float* __restrict__ betta,
                                  const float* __restrict__ gamma) {
    int n = blockIdx.x * blockDim.x + threadIdx.x;
    if (n < Ndim) {
        float a = fmaxf(alpha[0], 0.0f);
        float b = fmaxf(betta[n >> 6], 0.0f);
        float g = fmaxf(gamma[n & 63], 0.0f);
        g_scale[n] = a * b * g;
    }
}

// ---------------------------------------------------------------------------
// GEMM kernel: 128x256 output tile per CTA, 512 threads, warp tile 64x32.
// ---------------------------------------------------------------------------
DINL void fill_stage(uint32_t st_base, int m0, int n0, int kt, int tid) {
    const int k0 = kt * TK;
    // A: 128 rows x 128 B = 1024 x 16B chunks, 2 per thread
    #pragma unroll
    for (int i = 0; i < 2; i++) {
        int ch = tid + i * 512;
        uint32_t row = ch >> 3, cb = (ch & 7) * 16;
        cp_async16(st_base + swz(row, cb),
                   g_Xs + (size_t)(m0 + row) * Kdim + k0 + cb);
    }
    // B: 256 rows(N) x 128 B = 2048 chunks, 4 per thread
    uint32_t stB = st_base + A_BYTES;
    #pragma unroll
    for (int i = 0; i < 4; i++) {
        int ch = tid + i * 512;
        uint32_t row = ch >> 3, cb = (ch & 7) * 16;
        cp_async16(stB + swz(row, cb),
                   g_Wt + (size_t)(n0 + row) * Kdim + k0 + cb);
    }
}

__global__ void __launch_bounds__(512, 1) bgemm_kernel(float* __restrict__ out) {
    extern __shared__ char smem[];
    const uint32_t sb = smem_u32(smem);
    const int tid = threadIdx.x;
    const int wid = tid >> 5, lid = tid & 31;
    const int wm = wid >> 3;              // 0..1 : 64-row slab
    const int wn = wid & 7;               // 0..7 : 32-col slab
    const int m0 = blockIdx.y * TM;
    const int n0 = blockIdx.x * TN;

    int acc[4][4][4];                     // [mt][nt][4] s32 accumulators
    #pragma unroll
    for (int mt = 0; mt < 4; mt++)
        #pragma unroll
        for (int nt = 0; nt < 4; nt++)
            acc[mt][nt][0] = acc[mt][nt][1] = acc[mt][nt][2] = acc[mt][nt][3] = 0;

    // Prologue: fill stages 0..STAGES-2
    #pragma unroll
    for (int p = 0; p < STAGES - 1; p++) {
        fill_stage(sb + p * STAGE_BYTES, m0, n0, p, tid);
        cp_commit();
    }

    const uint32_t lrow = lid & 15;        // ldmatrix lane row
    const uint32_t lcol = (lid >> 4) * 16; // ldmatrix lane 16B col select

    // stage index helpers (mod 3 without division in the hot loop)
    int s_rd = 0;                          // it % 3
    int s_wr = STAGES - 1;                 // (it + STAGES-1) % 3

    for (int it = 0; it < KITERS; it++) {
        CP_WAIT_GROUP(STAGES - 2);         // stage `it` landed (this thread)
        __syncthreads();                   // visible to all; all warps past compute(it-1)

        // Fill the stage freed by compute(it-1); overlaps with compute below.
        const int jf = it + STAGES - 1;
        if (jf < KITERS)
            fill_stage(sb + s_wr * STAGE_BYTES, m0, n0, jf, tid);
        cp_commit();                       // empty group at the tail keeps counts uniform

        const uint32_t aBase = sb + s_rd * STAGE_BYTES;
        const uint32_t bBase = aBase + A_BYTES;

        #pragma unroll
        for (int ks = 0; ks < 4; ks++) {   // k32 steps across TK=128
            const uint32_t kb = ks * 32 + lcol;
            uint32_t af[4][4], bf[4][2];
            #pragma unroll
            for (int mt = 0; mt < 4; mt++) {
                uint32_t row = wm * 64 + mt * 16 + lrow;
                ldmatrix_x4(af[mt][0], af[mt][1], af[mt][2], af[mt][3],
                            aBase + swz(row, kb));
            }
            #pragma unroll
            for (int h = 0; h < 2; h++) {  // nt pairs (0,1) and (2,3)
                uint32_t nrow = wn * 32 + h * 16 + lrow;
                uint32_t r0, r1, r2, r3;
                ldmatrix_x4(r0, r1, r2, r3, bBase + swz(nrow, kb));
                bf[h * 2 + 0][0] = r0;  bf[h * 2 + 1][0] = r1;
                bf[h * 2 + 0][1] = r2;  bf[h * 2 + 1][1] = r3;
            }
            #pragma unroll
            for (int mt = 0; mt < 4; mt++)
                #pragma unroll
                for (int nt = 0; nt < 4; nt++)
                    imma(acc[mt][nt][0], acc[mt][nt][1],
                         acc[mt][nt][2], acc[mt][nt][3],
                         af[mt][0], af[mt][1], af[mt][2], af[mt][3],
                         bf[nt][0], bf[nt][1]);
        }

        if (++s_rd == STAGES) s_rd = 0;
        if (++s_wr == STAGES) s_wr = 0;
    }

    // Epilogue: scale and store. Thread t of each mma owns rows {g, g+8},
    // cols {c, c+1} with g = lid/4, c = (lid%4)*2.
    const int g  = lid >> 2;
    const int cc = (lid & 3) * 2;
    #pragma unroll
    for (int nt = 0; nt < 4; nt++) {
        const int col = n0 + wn * 32 + nt * 8 + cc;
        const float s0 = g_scale[col], s1 = g_scale[col + 1];
        #pragma unroll
        for (int mt = 0; mt < 4; mt++) {
            const int row = m0 + wm * 64 + mt * 16 + g;
            float2 v0 = make_float2((float)acc[mt][nt][0] * s0,
                                    (float)acc[mt][nt][1] * s1);
            float2 v1 = make_float2((float)acc[mt][nt][2] * s0,
                                    (float)acc[mt][nt][3] * s1);
            *reinterpret_cast<float2*>(out + (size_t)row * Ndim + col) = v0;
            *reinterpret_cast<float2*>(out + (size_t)(row + 8) * Ndim + col) = v1;
        }
    }
}

// ---------------------------------------------------------------------------
// Launch
// ---------------------------------------------------------------------------
extern "C" void kernel_launch(void* const* d_in, const int* in_sizes, int n_in,
                              void* d_out, int out_size) {
    const float* X     = (const float*)d_in[0];
    const float* W     = (const float*)d_in[1];
    const float* alpha = (const float*)d_in[2];
    const float* betta = (const float*)d_in[3];
    const float* gamma = (const float*)d_in[4];
    float* out = (float*)d_out;

    cudaFuncSetAttribute(bgemm_kernel, cudaFuncAttributeMaxDynamicSharedMemorySize, SMEM_BYTES);

    conv_x_kernel<<<16384, 256>>>(X);
    conv_w_kernel<<<dim3(Ndim / 32, Kdim / 32), dim3(32, 8)>>>(W);
    conv_scale_kernel<<<2, 1024>>>(alpha, betta, gamma);

    dim3 grid(Ndim / TN, Mdim / TM);   // (8, 64) = 512 CTAs
    bgemm_kernel<<<grid, 512, SMEM_BYTES>>>(out);
}

// round 7
// speedup vs baseline: 1.0031x; 1.0031x over previous
#include <cuda_runtime.h>
#include <cuda_bf16.h>
#include <cstdint>

// ============================================================================
// BinaryLinearLayer: out = sign(X) @ sign(W) * scale
// R3 evidence: GEMM was issue/latency-bound (tensor 52.3%, occ 12.5%, issue
// 29.7%, DRAM 3.3%). R4/R5 changes:
//   * 512-thread CTA (16 warps, 4/SMSP) with CTA tile 128x256 (warp 64x32)
//   * single __syncthreads per k-tile (wait -> sync -> fill(it+2) -> compute)
//   * STAGES=3 ring (144 KB SMEM)
// ============================================================================

#define DINL __device__ __forceinline__

static constexpr int Mdim = 8192, Ndim = 2048, Kdim = 4096;
static constexpr int TM = 128, TN = 256, TK = 128;       // int8: 128 B per K-row
static constexpr int STAGES = 3;
static constexpr int KITERS = Kdim / TK;                 // 32
static constexpr int A_BYTES = TM * TK;                  // 16384
static constexpr int B_BYTES = TN * TK;                  // 32768
static constexpr int STAGE_BYTES = A_BYTES + B_BYTES;    // 49152
static constexpr int SMEM_BYTES = STAGES * STAGE_BYTES;  // 147456

// ---------------------------------------------------------------------------
// Scratch (module globals; no runtime allocation)
// ---------------------------------------------------------------------------
__device__ int8_t g_Xs[(size_t)Mdim * Kdim];   // 32 MB  sign(X) int8 [M,K]
__device__ int8_t g_Wt[(size_t)Ndim * Kdim];   //  8 MB  sign(W)^T int8 [N,K]
__device__ float  g_scale[Ndim];

// ---------------------------------------------------------------------------
// PTX helpers (portable under target sm_100; no 'a'-suffix features)
// ---------------------------------------------------------------------------
DINL uint32_t smem_u32(const void* p) {
    uint32_t a;
    asm("{ .reg .u64 t; cvta.to.shared.u64 t, %1; cvt.u32.u64 %0, t; }" : "=r"(a) : "l"(p));
    return a;
}

DINL void cp_async16(uint32_t dst, const void* src) {
    asm volatile("cp.async.cg.shared.global [%0], [%1], 16;" :: "r"(dst), "l"(src));
}
DINL void cp_commit() { asm volatile("cp.async.commit_group;" ::: "memory"); }
#define CP_WAIT_GROUP(N) asm volatile("cp.async.wait_group %0;" :: "n"(N) : "memory")

DINL void ldmatrix_x4(uint32_t& r0, uint32_t& r1, uint32_t& r2, uint32_t& r3,
                      uint32_t addr) {
    asm volatile("ldmatrix.sync.aligned.m8n8.x4.shared.b16 {%0,%1,%2,%3}, [%4];"
                 : "=r"(r0), "=r"(r1), "=r"(r2), "=r"(r3) : "r"(addr));
}

DINL void imma(int& c0, int& c1, int& c2, int& c3,
               uint32_t a0, uint32_t a1, uint32_t a2, uint32_t a3,
               uint32_t b0, uint32_t b1) {
    asm volatile(
        "mma.sync.aligned.m16n8k32.row.col.s32.s8.s8.s32 "
        "{%0,%1,%2,%3}, {%4,%5,%6,%7}, {%8,%9}, {%0,%1,%2,%3};"
        : "+r"(c0), "+r"(c1), "+r"(c2), "+r"(c3)
        : "r"(a0), "r"(a1), "r"(a2), "r"(a3), "r"(b0), "r"(b1));
}

// byte-offset swizzle within 128B rows: spreads 8 rows across 16B banks
DINL uint32_t swz(uint32_t row, uint32_t kb) {   // kb < 128
    return row * 128u + (kb ^ ((row & 7u) << 4));
}

DINL int8_t sign_s8(float x) {
    return (int8_t)((x > 0.0f) - (x < 0.0f));    // sign(0) = 0, like jnp.sign
}

// ---------------------------------------------------------------------------
// Prepass kernels
// ---------------------------------------------------------------------------
__global__ void conv_x_kernel(const float* __restrict__ X) {
    size_t i = (size_t)blockIdx.x * blockDim.x + threadIdx.x;
    const float4* src = reinterpret_cast<const float4*>(X) + i * 2;
    float4 v0 = src[0], v1 = src[1];
    uint32_t lo = ((uint32_t)(uint8_t)sign_s8(v0.x)) |
                  ((uint32_t)(uint8_t)sign_s8(v0.y) << 8) |
                  ((uint32_t)(uint8_t)sign_s8(v0.z) << 16) |
                  ((uint32_t)(uint8_t)sign_s8(v0.w) << 24);
    uint32_t hi = ((uint32_t)(uint8_t)sign_s8(v1.x)) |
                  ((uint32_t)(uint8_t)sign_s8(v1.y) << 8) |
                  ((uint32_t)(uint8_t)sign_s8(v1.z) << 16) |
                  ((uint32_t)(uint8_t)sign_s8(v1.w) << 24);
    reinterpret_cast<uint2*>(g_Xs)[i] = make_uint2(lo, hi);
}

__global__ void conv_w_kernel(const float* __restrict__ W) {
    // W [4096(K), 2048(N)] row-major -> g_Wt [N, K] int8 signs (transposed)
    __shared__ float tile[32][33];
    int n0 = blockIdx.x * 32;   // along N
    int k0 = blockIdx.y * 32;   // along K
    int tx = threadIdx.x, ty = threadIdx.y;            // 32 x 8
    #pragma unroll
    for (int i = ty; i < 32; i += 8)
        tile[i][tx] = W[(size_t)(k0 + i) * Ndim + n0 + tx];
    __syncthreads();
    #pragma unroll
    for (int i = ty; i < 32; i += 8) {
        float v = tile[tx][i];                         // = W[k0+tx][n0+i]
        g_Wt[(size_t)(n0 + i) * Kdim + k0 + tx] = sign_s8(v);
    }
}

__global__ void conv_scale_kernel(const float* __restrict__ alpha,
                                  const float* __restrict__ betta,
                                  const float* __restrict__ gamma) {
    int n = blockIdx.x * blockDim.x + threadIdx.x;
    if (n < Ndim) {
        float a = fmaxf(alpha[0], 0.0f);
        float b = fmaxf(betta[n >> 6], 0.0f);
        float g = fmaxf(gamma[n & 63], 0.0f);
        g_scale[n] = a * b * g;
    }
}

// ---------------------------------------------------------------------------
// GEMM kernel: 128x256 output tile per CTA, 512 threads, warp tile 64x32.
// ---------------------------------------------------------------------------
DINL void fill_stage(uint32_t st_base, int m0, int n0, int kt, int tid) {
    const int k0 = kt * TK;
    // A: 128 rows x 128 B = 1024 x 16B chunks, 2 per thread
    #pragma unroll
    for (int i = 0; i < 2; i++) {
        int ch = tid + i * 512;
        uint32_t row = ch >> 3, cb = (ch & 7) * 16;
        cp_async16(st_base + swz(row, cb),
                   g_Xs + (size_t)(m0 + row) * Kdim + k0 + cb);
    }
    // B: 256 rows(N) x 128 B = 2048 chunks, 4 per thread
    uint32_t stB = st_base + A_BYTES;
    #pragma unroll
    for (int i = 0; i < 4; i++) {
        int ch = tid + i * 512;
        uint32_t row = ch >> 3, cb = (ch & 7) * 16;
        cp_async16(stB + swz(row, cb),
                   g_Wt + (size_t)(n0 + row) * Kdim + k0 + cb);
    }
}

__global__ void __launch_bounds__(512, 1) bgemm_kernel(float* __restrict__ out) {
    extern __shared__ char smem[];
    const uint32_t sb = smem_u32(smem);
    const int tid = threadIdx.x;
    const int wid = tid >> 5, lid = tid & 31;
    const int wm = wid >> 3;              // 0..1 : 64-row slab
    const int wn = wid & 7;               // 0..7 : 32-col slab
    const int m0 = blockIdx.y * TM;
    const int n0 = blockIdx.x * TN;

    int acc[4][4][4];                     // [mt][nt][4] s32 accumulators
    #pragma unroll
    for (int mt = 0; mt < 4; mt++)
        #pragma unroll
        for (int nt = 0; nt < 4; nt++)
            acc[mt][nt][0] = acc[mt][nt][1] = acc[mt][nt][2] = acc[mt][nt][3] = 0;

    // Prologue: fill stages 0..STAGES-2
    #pragma unroll
    for (int p = 0; p < STAGES - 1; p++) {
        fill_stage(sb + p * STAGE_BYTES, m0, n0, p, tid);
        cp_commit();
    }

    const uint32_t lrow = lid & 15;        // ldmatrix lane row
    const uint32_t lcol = (lid >> 4) * 16; // ldmatrix lane 16B col select

    // stage index helpers (mod 3 without division in the hot loop)
    int s_rd = 0;                          // it % 3
    int s_wr = STAGES - 1;                 // (it + STAGES-1) % 3

    for (int it = 0; it < KITERS; it++) {
        CP_WAIT_GROUP(STAGES - 2);         // stage `it` landed (this thread)
        __syncthreads();                   // visible to all; all warps past compute(it-1)

        // Fill the stage freed by compute(it-1); overlaps with compute below.
        const int jf = it + STAGES - 1;
        if (jf < KITERS)
            fill_stage(sb + s_wr * STAGE_BYTES, m0, n0, jf, tid);
        cp_commit();                       // empty group at the tail keeps counts uniform

        const uint32_t aBase = sb + s_rd * STAGE_BYTES;
        const uint32_t bBase = aBase + A_BYTES;

        #pragma unroll
        for (int ks = 0; ks < 4; ks++) {   // k32 steps across TK=128
            const uint32_t kb = ks * 32 + lcol;
            uint32_t af[4][4], bf[4][2];
            #pragma unroll
            for (int mt = 0; mt < 4; mt++) {
                uint32_t row = wm * 64 + mt * 16 + lrow;
                ldmatrix_x4(af[mt][0], af[mt][1], af[mt][2], af[mt][3],
                            aBase + swz(row, kb));
            }
            #pragma unroll
            for (int h = 0; h < 2; h++) {  // nt pairs (0,1) and (2,3)
                uint32_t nrow = wn * 32 + h * 16 + lrow;
                uint32_t r0, r1, r2, r3;
                ldmatrix_x4(r0, r1, r2, r3, bBase + swz(nrow, kb));
                bf[h * 2 + 0][0] = r0;  bf[h * 2 + 1][0] = r1;
                bf[h * 2 + 0][1] = r2;  bf[h * 2 + 1][1] = r3;
            }
            #pragma unroll
            for (int mt = 0; mt < 4; mt++)
                #pragma unroll
                for (int nt = 0; nt < 4; nt++)
                    imma(acc[mt][nt][0], acc[mt][nt][1],
                         acc[mt][nt][2], acc[mt][nt][3],
                         af[mt][0], af[mt][1], af[mt][2], af[mt][3],
                         bf[nt][0], bf[nt][1]);
        }

        if (++s_rd == STAGES) s_rd = 0;
        if (++s_wr == STAGES) s_wr = 0;
    }

    // Epilogue: scale and store. Thread t of each mma owns rows {g, g+8},
    // cols {c, c+1} with g = lid/4, c = (lid%4)*2.
    const int g  = lid >> 2;
    const int cc = (lid & 3) * 2;
    #pragma unroll
    for (int nt = 0; nt < 4; nt++) {
        const int col = n0 + wn * 32 + nt * 8 + cc;
        const float s0 = g_scale[col], s1 = g_scale[col + 1];
        #pragma unroll
        for (int mt = 0; mt < 4; mt++) {
            const int row = m0 + wm * 64 + mt * 16 + g;
            float2 v0 = make_float2((float)acc[mt][nt][0] * s0,
                                    (float)acc[mt][nt][1] * s1);
            float2 v1 = make_float2((float)acc[mt][nt][2] * s0,
                                    (float)acc[mt][nt][3] * s1);
            *reinterpret_cast<float2*>(out + (size_t)row * Ndim + col) = v0;
            *reinterpret_cast<float2*>(out + (size_t)(row + 8) * Ndim + col) = v1;
        }
    }
}

// ---------------------------------------------------------------------------
// Launch
// ---------------------------------------------------------------------------
extern "C" void kernel_launch(void* const* d_in, const int* in_sizes, int n_in,
                              void* d_out, int out_size) {
    const float* X     = (const float*)d_in[0];
    const float* W     = (const float*)d_in[1];
    const float* alpha = (const float*)d_in[2];
    const float* betta = (const float*)d_in[3];
    const float* gamma = (const float*)d_in[4];
    float* out = (float*)d_out;

    cudaFuncSetAttribute(bgemm_kernel, cudaFuncAttributeMaxDynamicSharedMemorySize, SMEM_BYTES);

    conv_x_kernel<<<16384, 256>>>(X);
    conv_w_kernel<<<dim3(Ndim / 32, Kdim / 32), dim3(32, 8)>>>(W);
    conv_scale_kernel<<<2, 1024>>>(alpha, betta, gamma);

    dim3 grid(Ndim / TN, Mdim / TM);   // (8, 64) = 512 CTAs
    bgemm_kernel<<<grid, 512, SMEM_BYTES>>>(out);
}